// round 8
// baseline (speedup 1.0000x reference)
#include <cuda_runtime.h>

#define NB 256
#define NT 64

__device__ float        g_partials[NB];
__device__ unsigned int g_bar;   // monotonic ticket counter (never reset)

__global__ void __launch_bounds__(NT, 8)
ril_fused_kernel(const float* __restrict__ x,
                 const float* __restrict__ weights,
                 const float* __restrict__ min_vals,
                 const float* __restrict__ max_vals,
                 const int* __restrict__ start_pos,
                 const int* __restrict__ offsets,
                 const int* __restrict__ sizes,
                 const int* __restrict__ out_mask,
                 float* __restrict__ out,
                 int B, int D, int G, int Wn, int OUTN, int total)
{
    extern __shared__ float smv[];  // G floats: min_vals

    const int lane = threadIdx.x & 31;
    const int w    = threadIdx.x >> 5;
    const float inv_b = 1.0f / (float)B;

    // Vectorized preload of min_vals (G % 4 == 0 path; scalar fallback otherwise)
    if ((G & 3) == 0) {
        const float4* mv4 = (const float4*)min_vals;
        for (int i = threadIdx.x; i < (G >> 2); i += NT) {
            float4 m = __ldg(&mv4[i]);
            smv[i * 4 + 0] = m.x; smv[i * 4 + 1] = m.y;
            smv[i * 4 + 2] = m.z; smv[i * 4 + 3] = m.w;
        }
    } else {
        for (int i = threadIdx.x; i < G; i += NT) smv[i] = __ldg(&min_vals[i]);
    }
    __syncthreads();

    // ---- Phase 1: 4 consecutive columns per thread (float4 row loads) ----
    float acc = 0.0f;
    const int nchunk = D >> 2;                    // full float4 chunks
    const int cstride = (int)gridDim.x * NT;
    for (int chunk = blockIdx.x * NT + threadIdx.x; chunk < nchunk; chunk += cstride) {
        float4 s4 = make_float4(0.f, 0.f, 0.f, 0.f);
        #pragma unroll 8
        for (int b = 0; b < B; ++b) {
            const float4 xv = __ldg((const float4*)(x + (size_t)b * D) + chunk);
            s4.x += xv.x; s4.y += xv.y; s4.z += xv.z; s4.w += xv.w;
        }
        const float v[4] = { s4.x * inv_b, s4.y * inv_b, s4.z * inv_b, s4.w * inv_b };

        #pragma unroll
        for (int k = 0; k < 4; ++k) {
            const float vv = v[k];
            const int col = chunk * 4 + k;
            int lo = 0, hi = G;
            while (lo < hi) {
                int mid = (lo + hi) >> 1;
                if (smv[mid] <= vv) lo = mid + 1; else hi = mid;
            }
            const int g  = lo - 1;
            const int gc = min(max(g, 0), G - 1);
            bool in_range = (g >= 0) && (vv >= smv[gc]) && (vv <= __ldg(&max_vals[gc]));
            int pos = col - __ldg(&start_pos[gc]);
            bool valid = in_range && (pos >= 0) && (pos < __ldg(&sizes[gc]));
            int widx = __ldg(&offsets[gc]) + pos;
            widx = min(max(widx, 0), Wn - 1);
            float wv = valid ? __ldg(&weights[widx]) : 0.0f;
            acc += vv * wv;
        }
    }
    // Scalar tail for D % 4 != 0 (handled by block 0 only)
    if (blockIdx.x == 0) {
        for (int col = nchunk * 4 + threadIdx.x; col < D; col += NT) {
            float s = 0.0f;
            for (int b = 0; b < B; ++b) s += x[(size_t)b * D + col];
            const float vv = s * inv_b;
            int lo = 0, hi = G;
            while (lo < hi) {
                int mid = (lo + hi) >> 1;
                if (smv[mid] <= vv) lo = mid + 1; else hi = mid;
            }
            const int g  = lo - 1;
            const int gc = min(max(g, 0), G - 1);
            bool in_range = (g >= 0) && (vv >= smv[gc]) && (vv <= max_vals[gc]);
            int pos = col - start_pos[gc];
            bool valid = in_range && (pos >= 0) && (pos < sizes[gc]);
            int widx = offsets[gc] + pos;
            widx = min(max(widx, 0), Wn - 1);
            acc += vv * (valid ? weights[widx] : 0.0f);
        }
    }

    // ---- Block reduce (NT = 64: two warps) ----
    #pragma unroll
    for (int o = 16; o > 0; o >>= 1)
        acc += __shfl_down_sync(0xffffffffu, acc, o);
    __shared__ float red[NT / 32];
    if (lane == 0) red[w] = acc;
    __syncthreads();
    if (threadIdx.x == 0) {
        float p = 0.0f;
        #pragma unroll
        for (int k = 0; k < NT / 32; ++k) p += red[k];
        g_partials[blockIdx.x] = p;
    }

    // ---- Device-wide ticket barrier (monotonic; survives graph replays) ----
    if (threadIdx.x == 0) {
        __threadfence();
        unsigned int arrival = atomicAdd(&g_bar, 1u) + 1u;
        unsigned int target  = ((arrival - 1u) / gridDim.x + 1u) * gridDim.x;
        unsigned int c;
        do {
            asm volatile("ld.acquire.gpu.u32 %0, [%1];" : "=r"(c) : "l"(&g_bar));
        } while (c < target);
    }
    __syncthreads();

    // ---- Phase 2: all blocks sum partials with a fixed deterministic tree ----
    float a2 = 0.0f;
    for (int i = threadIdx.x; i < (int)gridDim.x; i += NT)
        a2 += *(volatile float*)&g_partials[i];
    #pragma unroll
    for (int o = 16; o > 0; o >>= 1)
        a2 += __shfl_down_sync(0xffffffffu, a2, o);
    __shared__ float red2[NT / 32];
    __shared__ float s_val;
    if (lane == 0) red2[w] = a2;
    __syncthreads();
    if (threadIdx.x == 0) {
        float s = 0.0f;
        #pragma unroll
        for (int k = 0; k < NT / 32; ++k) s += red2[k];
        s_val = s;
    }
    __syncthreads();
    const float s = s_val;

    // ---- Output: each block writes its contiguous slice, vectorized ----
    const int per = (total + (int)gridDim.x - 1) / (int)gridDim.x;
    const int j0  = blockIdx.x * per;
    const int j1  = min(j0 + per, total);

    if ((j0 & 3) == 0 && (per & 3) == 0 && (OUTN & 3) == 0) {
        for (int j = j0 + threadIdx.x * 4; j < j1; j += NT * 4) {
            float4 o4 = make_float4(0.f, 0.f, 0.f, 0.f);
            if (j + 3 < OUTN) {
                const int4 m4 = __ldg((const int4*)(out_mask + j));
                o4.x = m4.x ? s : 0.0f;
                o4.y = m4.y ? s : 0.0f;
                o4.z = m4.z ? s : 0.0f;
                o4.w = m4.w ? s : 0.0f;
            }
            *(float4*)(out + j) = o4;
        }
    } else {
        for (int j = j0 + threadIdx.x; j < j1; j += NT) {
            float o = 0.0f;
            if (j < OUTN) o = (__ldg(&out_mask[j]) != 0) ? s : 0.0f;
            out[j] = o;
        }
    }
}

extern "C" void kernel_launch(void* const* d_in, const int* in_sizes, int n_in,
                              void* d_out, int out_size)
{
    const float* x        = (const float*)d_in[0];
    const float* weights  = (const float*)d_in[1];
    const float* min_vals = (const float*)d_in[2];
    const float* max_vals = (const float*)d_in[3];
    const int*   start_p  = (const int*)d_in[4];
    const int*   offsets  = (const int*)d_in[5];
    const int*   sizes    = (const int*)d_in[6];
    const int*   out_mask = (const int*)d_in[7];
    float* out = (float*)d_out;

    int G  = in_sizes[2];
    int Wn = in_sizes[1];
    int D  = Wn / G;
    int B  = in_sizes[0] / D;
    int OUTN = in_sizes[7];

    size_t shmem = (size_t)G * sizeof(float);
    ril_fused_kernel<<<NB, NT, shmem>>>(
        x, weights, min_vals, max_vals, start_p, offsets, sizes,
        out_mask, out, B, D, G, Wn, OUTN, out_size);
}

// round 9
// speedup vs baseline: 1.3333x; 1.3333x over previous
#include <cuda_runtime.h>

#define NB 256
#define NT 256

__device__ float        g_partials[NB];
__device__ unsigned int g_bar;   // monotonic ticket counter (never reset)

__global__ void __launch_bounds__(NT, 2)
ril_fused_kernel(const float* __restrict__ x,
                 const float* __restrict__ weights,
                 const float* __restrict__ min_vals,
                 const float* __restrict__ max_vals,
                 const int* __restrict__ start_pos,
                 const int* __restrict__ offsets,
                 const int* __restrict__ sizes,
                 const int* __restrict__ out_mask,
                 float* __restrict__ out,
                 int B, int D, int G, int Wn, int OUTN, int total)
{
    // Shared: G floats (min_vals) then G int4 (packed {max,start,off,size})
    extern __shared__ float smv[];
    int4* stab = (int4*)(smv + G);

    const int lane = threadIdx.x & 31;
    const int w    = threadIdx.x >> 5;
    const float inv_b = 1.0f / (float)B;

    // Preload min_vals + packed table (independent loads, one burst)
    for (int i = threadIdx.x; i < G; i += NT) {
        smv[i] = __ldg(&min_vals[i]);
        int4 e;
        e.x = __float_as_int(__ldg(&max_vals[i]));
        e.y = __ldg(&start_pos[i]);
        e.z = __ldg(&offsets[i]);
        e.w = __ldg(&sizes[i]);
        stab[i] = e;
    }
    __syncthreads();

    // ---- Phase 1: one column per thread, grid-stride ----
    float acc = 0.0f;
    const int stride = (int)gridDim.x * NT;
    for (int col = blockIdx.x * NT + threadIdx.x; col < D; col += stride) {
        // B independent coalesced row loads
        float s = 0.0f;
        #pragma unroll 8
        for (int b = 0; b < B; ++b)
            s += __ldg(x + (size_t)b * D + col);
        const float vv = s * inv_b;

        // searchsorted(min_vals, v, 'right') - 1
        int lo = 0, hi = G;
        while (lo < hi) {
            int mid = (lo + hi) >> 1;
            if (smv[mid] <= vv) lo = mid + 1; else hi = mid;
        }
        const int g  = lo - 1;
        const int gc = min(max(g, 0), G - 1);

        // Single 16B shared load replaces 4 global gathers
        const int4 e = stab[gc];
        const float mx   = __int_as_float(e.x);
        const int   sp   = e.y;
        const int   off  = e.z;
        const int   sz   = e.w;

        bool in_range = (g >= 0) && (vv >= smv[gc]) && (vv <= mx);
        int pos = col - sp;
        bool valid = in_range && (pos >= 0) && (pos < sz);
        int widx = off + pos;
        widx = min(max(widx, 0), Wn - 1);
        float wv = valid ? __ldg(&weights[widx]) : 0.0f;
        acc += vv * wv;
    }

    // ---- Block reduce ----
    #pragma unroll
    for (int o = 16; o > 0; o >>= 1)
        acc += __shfl_down_sync(0xffffffffu, acc, o);
    __shared__ float red[NT / 32];
    if (lane == 0) red[w] = acc;
    __syncthreads();
    if (threadIdx.x == 0) {
        float p = 0.0f;
        #pragma unroll
        for (int k = 0; k < NT / 32; ++k) p += red[k];
        g_partials[blockIdx.x] = p;
    }

    // ---- Device-wide ticket barrier (monotonic; survives graph replays) ----
    if (threadIdx.x == 0) {
        __threadfence();
        unsigned int arrival = atomicAdd(&g_bar, 1u) + 1u;
        unsigned int target  = ((arrival - 1u) / gridDim.x + 1u) * gridDim.x;
        unsigned int c;
        do {
            asm volatile("ld.acquire.gpu.u32 %0, [%1];" : "=r"(c) : "l"(&g_bar));
        } while (c < target);
    }
    __syncthreads();

    // ---- Phase 2: all blocks sum partials with a fixed deterministic tree ----
    float a2 = 0.0f;
    for (int i = threadIdx.x; i < (int)gridDim.x; i += NT)
        a2 += *(volatile float*)&g_partials[i];
    #pragma unroll
    for (int o = 16; o > 0; o >>= 1)
        a2 += __shfl_down_sync(0xffffffffu, a2, o);
    __shared__ float red2[NT / 32];
    __shared__ float s_val;
    if (lane == 0) red2[w] = a2;
    __syncthreads();
    if (threadIdx.x == 0) {
        float s = 0.0f;
        #pragma unroll
        for (int k = 0; k < NT / 32; ++k) s += red2[k];
        s_val = s;
    }
    __syncthreads();
    const float s = s_val;

    // ---- Output: each block writes its contiguous slice, vectorized ----
    const int per = (total + (int)gridDim.x - 1) / (int)gridDim.x;
    const int j0  = blockIdx.x * per;
    const int j1  = min(j0 + per, total);

    if ((j0 & 3) == 0 && (per & 3) == 0 && (OUTN & 3) == 0) {
        for (int j = j0 + threadIdx.x * 4; j < j1; j += NT * 4) {
            float4 o4 = make_float4(0.f, 0.f, 0.f, 0.f);
            if (j + 3 < OUTN) {
                const int4 m4 = __ldg((const int4*)(out_mask + j));
                o4.x = m4.x ? s : 0.0f;
                o4.y = m4.y ? s : 0.0f;
                o4.z = m4.z ? s : 0.0f;
                o4.w = m4.w ? s : 0.0f;
            }
            *(float4*)(out + j) = o4;
        }
    } else {
        for (int j = j0 + threadIdx.x; j < j1; j += NT) {
            float o = 0.0f;
            if (j < OUTN) o = (__ldg(&out_mask[j]) != 0) ? s : 0.0f;
            out[j] = o;
        }
    }
}

extern "C" void kernel_launch(void* const* d_in, const int* in_sizes, int n_in,
                              void* d_out, int out_size)
{
    const float* x        = (const float*)d_in[0];
    const float* weights  = (const float*)d_in[1];
    const float* min_vals = (const float*)d_in[2];
    const float* max_vals = (const float*)d_in[3];
    const int*   start_p  = (const int*)d_in[4];
    const int*   offsets  = (const int*)d_in[5];
    const int*   sizes    = (const int*)d_in[6];
    const int*   out_mask = (const int*)d_in[7];
    float* out = (float*)d_out;

    int G  = in_sizes[2];
    int Wn = in_sizes[1];
    int D  = Wn / G;
    int B  = in_sizes[0] / D;
    int OUTN = in_sizes[7];

    size_t shmem = (size_t)G * (sizeof(float) + sizeof(int4));
    ril_fused_kernel<<<NB, NT, shmem>>>(
        x, weights, min_vals, max_vals, start_p, offsets, sizes,
        out_mask, out, B, D, G, Wn, OUTN, out_size);
}